// round 16
// baseline (speedup 1.0000x reference)
#include <cuda_runtime.h>
#include <cuda_fp16.h>
#include <math.h>
#include <float.h>

// ---------------- problem constants ----------------
#define NN      50000
#define NE      600000
#define DD      128
#define NET     4
#define NSTEPS  5
#define NHEADS  2
#define NG      64
#define NCLS    32

// ---------------- device scratch (duplicated per graph for stream overlap) ----------------
__device__ __half g_h_h [2][NN * DD];
__device__ __half g_a_h [2][NN * DD];
__device__ __half g_t_h [2][(size_t)NN * NET * DD];
__device__ __half g_gh_h[2][NN * 3 * DD];
__device__ __half g_zft_h[2][NN * NHEADS * DD];
__device__ float  g_el  [2][NN * NHEADS];
__device__ float  g_er  [2][NN * NHEADS];
__device__ float  g_wgt [2][NE * NHEADS];
__device__ float  g_rst [2][NN * NHEADS * DD];
__device__ float  g_logits[2][NG * NHEADS * NCLS];

// fp16 weights (shared, converted once per launch before fork)
__device__ __half g_Wet_h[NET * DD * DD];
__device__ __half g_Whh_h[3 * DD * DD];
__device__ __half g_Wih_h[3 * DD * DD];
__device__ __half g_Wfc_h[NHEADS * DD * DD];

__device__ int g_deg   [2][NN];
__device__ int g_indptr[2][NN + 1];
__device__ int g_cursor[2][NN];
__device__ int g_pk    [2][NE];
__device__ int g_epos  [2][NE];
__device__ int g_gs    [2][NG + 1];
__device__ int g_bsum  [2][64];

__device__ __forceinline__ float sigf(float x) { return 1.f / (1.f + expf(-x)); }

__device__ __forceinline__ float4 h4tof4(uint2 v) {
    float2 a = __half22float2(*(__half2*)&v.x);
    float2 b = __half22float2(*(__half2*)&v.y);
    return make_float4(a.x, a.y, b.x, b.y);
}
__device__ __forceinline__ uint2 f4toh4(float4 v) {
    uint2 o;
    *(__half2*)&o.x = __floats2half2_rn(v.x, v.y);
    *(__half2*)&o.y = __floats2half2_rn(v.z, v.w);
    return o;
}

// ---------------- misc small kernels ----------------
__global__ void conv_w(const float* __restrict__ src, __half* __restrict__ dst, int n) {
    int i = blockIdx.x * blockDim.x + threadIdx.x;
    if (i < n / 2) {
        float2 v = ((const float2*)src)[i];
        ((__half2*)dst)[i] = __floats2half2_rn(v.x, v.y);
    }
}

__global__ void copy_h(int g, const float* __restrict__ f) {
    int i = blockIdx.x * blockDim.x + threadIdx.x;
    if (i < NN * (DD / 4)) {
        float4 v = ((const float4*)f)[i];
        ((uint2*)g_h_h[g])[i] = f4toh4(v);
    }
}

__global__ void zero_deg(int g) {
    int i = blockIdx.x * blockDim.x + threadIdx.x;
    if (i < NN) g_deg[g][i] = 0;
}

__global__ void count_deg(int g, const int* __restrict__ dst) {
    int e = blockIdx.x * blockDim.x + threadIdx.x;
    if (e < NE) atomicAdd(&g_deg[g][dst[e]], 1);
}

// ---- multi-block scan: 49 blocks x 1024 ----
__global__ void scan1(int g) {
    __shared__ int wsum[32];
    int tid = threadIdx.x;
    int i = blockIdx.x * 1024 + tid;
    int v = (i < NN) ? g_deg[g][i] : 0;
    int x = v;
    #pragma unroll
    for (int o = 1; o < 32; o <<= 1) {
        int y = __shfl_up_sync(0xffffffffu, x, o);
        if ((tid & 31) >= o) x += y;
    }
    if ((tid & 31) == 31) wsum[tid >> 5] = x;
    __syncthreads();
    if (tid < 32) {
        int wv = wsum[tid];
        int xs = wv;
        #pragma unroll
        for (int o = 1; o < 32; o <<= 1) {
            int y = __shfl_up_sync(0xffffffffu, xs, o);
            if (tid >= o) xs += y;
        }
        wsum[tid] = xs - wv;
    }
    __syncthreads();
    int excl = (x - v) + wsum[tid >> 5];
    if (i < NN) g_indptr[g][i] = excl;
    if (tid == 1023) g_bsum[g][blockIdx.x] = excl + v;
}

__global__ void scan2(int g) {
    int s = 0;
    for (int b = 0; b < 49; b++) { int t = g_bsum[g][b]; g_bsum[g][b] = s; s += t; }
    g_indptr[g][NN] = s;
}

__global__ void scan3(int g) {
    int i = blockIdx.x * 1024 + threadIdx.x;
    if (i < NN) {
        int v = g_indptr[g][i] + g_bsum[g][blockIdx.x];
        g_indptr[g][i] = v;
        g_cursor[g][i] = v;
    }
}

__global__ void build_eids(int g, const int* __restrict__ src, const int* __restrict__ dst,
                           const int* __restrict__ et) {
    int e = blockIdx.x * blockDim.x + threadIdx.x;
    if (e < NE) {
        int p = atomicAdd(&g_cursor[g][dst[e]], 1);
        g_pk[g][p] = src[e] | (et[e] << 16);
        g_epos[g][e] = p;
    }
}

// ---------------- FP16 tensor-core GEMM (K=128), A+B staged in smem ----------------
#define S2 68
#define TILE_H2 (128 * S2)

__device__ __forceinline__ void gemm_body(
    const __half* __restrict__ A, const __half* __restrict__ Bw,
    const float* __restrict__ bias, __half* __restrict__ C,
    int outDim, int rowBase, int colBase, __half2* As2, __half2* Bs2)
{
    const int tid = threadIdx.x;
    const int lane = tid & 31, wid = tid >> 5;
    const int wm = wid >> 2, wn = wid & 3;
    const int g8 = lane >> 2, t4 = lane & 3;

    float c[4][4][4];
    #pragma unroll
    for (int mt = 0; mt < 4; mt++)
        #pragma unroll
        for (int nt = 0; nt < 4; nt++)
            #pragma unroll
            for (int i = 0; i < 4; i++) c[mt][nt][i] = 0.f;

    const int lr = tid >> 1;
    const int lh2 = (tid & 1) * 16;
    const int ga = rowBase + lr;
    const int aBytes = (ga < NN) ? 16 : 0;
    const __half* Ap = A + (size_t)ga * 128;
    const __half* Bp = Bw + (size_t)(colBase + lr) * 128;
    const unsigned aDst = (unsigned)__cvta_generic_to_shared(&As2[lr * S2 + lh2]);
    const unsigned bDst = (unsigned)__cvta_generic_to_shared(&Bs2[lr * S2 + lh2]);

    #pragma unroll
    for (int ch = 0; ch < 2; ch++) {
        #pragma unroll
        for (int i = 0; i < 4; i++) {
            asm volatile("cp.async.cg.shared.global [%0], [%1], 16, %2;"
                :: "r"(aDst + ch * 128 + i * 16),
                   "l"(Ap + ch * 64 + lh2 * 2 + i * 8), "r"(aBytes));
            asm volatile("cp.async.cg.shared.global [%0], [%1], 16;"
                :: "r"(bDst + ch * 128 + i * 16),
                   "l"(Bp + ch * 64 + lh2 * 2 + i * 8));
        }
        asm volatile("cp.async.commit_group;");
    }

    #pragma unroll
    for (int ch = 0; ch < 2; ch++) {
        if (ch == 0) asm volatile("cp.async.wait_group 1;");
        else         asm volatile("cp.async.wait_group 0;");
        __syncthreads();
        #pragma unroll
        for (int ks = 0; ks < 4; ks++) {
            const int kb = ch * 32 + ks * 8;
            unsigned af[4][4], bf[4][2];
            #pragma unroll
            for (int mt = 0; mt < 4; mt++) {
                int r0 = wm * 64 + mt * 16 + g8;
                af[mt][0] = *(unsigned*)&As2[r0 * S2 + kb + t4];
                af[mt][1] = *(unsigned*)&As2[(r0 + 8) * S2 + kb + t4];
                af[mt][2] = *(unsigned*)&As2[r0 * S2 + kb + 4 + t4];
                af[mt][3] = *(unsigned*)&As2[(r0 + 8) * S2 + kb + 4 + t4];
            }
            #pragma unroll
            for (int nt = 0; nt < 4; nt++) {
                int n0 = wn * 32 + nt * 8 + g8;
                bf[nt][0] = *(unsigned*)&Bs2[n0 * S2 + kb + t4];
                bf[nt][1] = *(unsigned*)&Bs2[n0 * S2 + kb + 4 + t4];
            }
            #pragma unroll
            for (int mt = 0; mt < 4; mt++)
                #pragma unroll
                for (int nt = 0; nt < 4; nt++) {
                    asm volatile(
                        "mma.sync.aligned.m16n8k16.row.col.f32.f16.f16.f32 "
                        "{%0,%1,%2,%3}, {%4,%5,%6,%7}, {%8,%9}, {%0,%1,%2,%3};\n"
                        : "+f"(c[mt][nt][0]), "+f"(c[mt][nt][1]),
                          "+f"(c[mt][nt][2]), "+f"(c[mt][nt][3])
                        : "r"(af[mt][0]), "r"(af[mt][1]), "r"(af[mt][2]), "r"(af[mt][3]),
                          "r"(bf[nt][0]), "r"(bf[nt][1]));
                }
        }
    }

    #pragma unroll
    for (int mt = 0; mt < 4; mt++) {
        int r0 = rowBase + wm * 64 + mt * 16 + g8;
        #pragma unroll
        for (int nt = 0; nt < 4; nt++) {
            int col = colBase + wn * 32 + nt * 8 + 2 * t4;
            float b0 = bias ? bias[col] : 0.f;
            float b1 = bias ? bias[col + 1] : 0.f;
            if (r0 < NN)
                *(__half2*)(C + (size_t)r0 * outDim + col) =
                    __floats2half2_rn(c[mt][nt][0] + b0, c[mt][nt][1] + b1);
            if (r0 + 8 < NN)
                *(__half2*)(C + (size_t)(r0 + 8) * outDim + col) =
                    __floats2half2_rn(c[mt][nt][2] + b0, c[mt][nt][3] + b1);
        }
    }
}

// mode 0: fused et (y<4 -> t) + hh (y>=4 -> gh), A = h
// mode 2: zft (A = h, C = zft, no bias)
__global__ __launch_bounds__(256, 2)
void gemm_all(int mode, int g, const float* __restrict__ b0, const float* __restrict__ b1) {
    extern __shared__ __half2 sm2[];
    __half2* As2 = sm2;
    __half2* Bs2 = sm2 + TILE_H2;
    int y = blockIdx.y;
    const __half* A; const __half* Bw; const float* bias; __half* C;
    int outDim, colBase;
    if (mode == 0) {
        A = g_h_h[g];
        if (y < 4) { Bw = g_Wet_h; bias = b0; C = g_t_h[g];  outDim = 512; colBase = y * 128; }
        else       { Bw = g_Whh_h; bias = b1; C = g_gh_h[g]; outDim = 384; colBase = (y - 4) * 128; }
    } else {
        A = g_h_h[g]; Bw = g_Wfc_h; bias = nullptr; C = g_zft_h[g]; outDim = 256; colBase = y * 128;
    }
    gemm_body(A, Bw, bias, C, outDim, blockIdx.x * 128, colBase, As2, Bs2);
}

// ---------------- fused gi GEMM + GRU (64-row blocks) ----------------
// Computes gi = a @ W_ih^T for all 3 gate tiles in registers, then applies the
// GRU update reading gh + h from global and writing h only. gi never hits DRAM.
#define GRU_A_H2 (64 * S2)
#define GRU_SMEM ((GRU_A_H2 + 2 * TILE_H2) * 4)

__global__ __launch_bounds__(256, 1)
void gemm_gru(int g, const float* __restrict__ b_ih) {
    extern __shared__ __half2 sm2[];
    __half2* As2 = sm2;                    // 64 x S2
    __half2* Bs2 = sm2 + GRU_A_H2;         // 2 x 128 x S2
    const int tid = threadIdx.x;
    const int lane = tid & 31, wid = tid >> 5;
    const int wm = wid >> 2, wn = wid & 3;       // 2 x 4 warp grid -> 32x32 per warp
    const int g8 = lane >> 2, t4 = lane & 3;
    const int rowBase = blockIdx.x * 64;

    float c[3][2][4][4];
    #pragma unroll
    for (int y = 0; y < 3; y++)
        #pragma unroll
        for (int mt = 0; mt < 2; mt++)
            #pragma unroll
            for (int nt = 0; nt < 4; nt++)
                #pragma unroll
                for (int i = 0; i < 4; i++) c[y][mt][nt][i] = 0.f;

    // --- A staging: 64 rows x 128 halves (4x16B per thread) ---
    {
        const int alr = tid >> 2;          // row 0..63
        const int aq  = tid & 3;           // quarter of row
        const int ga = rowBase + alr;
        const int aBytes = (ga < NN) ? 16 : 0;
        const __half* Ap = g_a_h[g] + (size_t)ga * 128 + aq * 32;
        const unsigned aDst = (unsigned)__cvta_generic_to_shared(&As2[alr * S2 + aq * 16]);
        #pragma unroll
        for (int j = 0; j < 4; j++)
            asm volatile("cp.async.cg.shared.global [%0], [%1], 16, %2;"
                :: "r"(aDst + j * 16), "l"(Ap + j * 8), "r"(aBytes));
    }

    // --- B staging helper: tile y into buffer b (8x16B per thread) ---
    const int blr = tid >> 1;
    const int bh2 = (tid & 1) * 32;        // half2 offset within row
    const unsigned bDstBase = (unsigned)__cvta_generic_to_shared(&Bs2[blr * S2 + bh2]);
    #define STAGE_B(y, b) do {                                                    \
        const __half* Bp = g_Wih_h + (size_t)((y) * 128 + blr) * 128 + bh2 * 2;   \
        _Pragma("unroll")                                                         \
        for (int j = 0; j < 8; j++)                                               \
            asm volatile("cp.async.cg.shared.global [%0], [%1], 16;"              \
                :: "r"(bDstBase + (b) * (TILE_H2 * 4) + j * 16), "l"(Bp + j * 8)); \
        asm volatile("cp.async.commit_group;");                                   \
    } while (0)

    STAGE_B(0, 0);   // group 0 = A + B0
    STAGE_B(1, 1);   // group 1 = B1

    #define COMPUTE_TILE(y, b) do {                                               \
        _Pragma("unroll")                                                         \
        for (int ks = 0; ks < 8; ks++) {                                          \
            const int kb = ks * 8;                                                \
            unsigned af[2][4], bf[4][2];                                          \
            _Pragma("unroll")                                                     \
            for (int mt = 0; mt < 2; mt++) {                                      \
                int r0 = wm * 32 + mt * 16 + g8;                                  \
                af[mt][0] = *(unsigned*)&As2[r0 * S2 + kb + t4];                  \
                af[mt][1] = *(unsigned*)&As2[(r0 + 8) * S2 + kb + t4];            \
                af[mt][2] = *(unsigned*)&As2[r0 * S2 + kb + 4 + t4];              \
                af[mt][3] = *(unsigned*)&As2[(r0 + 8) * S2 + kb + 4 + t4];        \
            }                                                                     \
            _Pragma("unroll")                                                     \
            for (int nt = 0; nt < 4; nt++) {                                      \
                int n0 = wn * 32 + nt * 8 + g8;                                   \
                bf[nt][0] = *(unsigned*)&Bs2[(b) * TILE_H2 + n0 * S2 + kb + t4];  \
                bf[nt][1] = *(unsigned*)&Bs2[(b) * TILE_H2 + n0 * S2 + kb + 4 + t4]; \
            }                                                                     \
            _Pragma("unroll")                                                     \
            for (int mt = 0; mt < 2; mt++)                                        \
                _Pragma("unroll")                                                 \
                for (int nt = 0; nt < 4; nt++) {                                  \
                    asm volatile(                                                 \
                        "mma.sync.aligned.m16n8k16.row.col.f32.f16.f16.f32 "      \
                        "{%0,%1,%2,%3}, {%4,%5,%6,%7}, {%8,%9}, {%0,%1,%2,%3};\n" \
                        : "+f"(c[y][mt][nt][0]), "+f"(c[y][mt][nt][1]),           \
                          "+f"(c[y][mt][nt][2]), "+f"(c[y][mt][nt][3])            \
                        : "r"(af[mt][0]), "r"(af[mt][1]), "r"(af[mt][2]), "r"(af[mt][3]), \
                          "r"(bf[nt][0]), "r"(bf[nt][1]));                        \
                }                                                                 \
        }                                                                         \
    } while (0)

    asm volatile("cp.async.wait_group 1;");   // A + B0 ready
    __syncthreads();
    COMPUTE_TILE(0, 0);
    __syncthreads();                           // all warps done with Bs[0]
    STAGE_B(2, 0);                             // group 2 = B2 into buffer 0
    asm volatile("cp.async.wait_group 1;");    // B1 ready
    __syncthreads();
    COMPUTE_TILE(1, 1);
    asm volatile("cp.async.wait_group 0;");    // B2 ready
    __syncthreads();
    COMPUTE_TILE(2, 0);
    #undef STAGE_B
    #undef COMPUTE_TILE

    // --- GRU epilogue: thread owns gi (r,z,n) at its (row,col) pairs ---
    const __half* ghb = g_gh_h[g];
    __half* hb = g_h_h[g];
    #pragma unroll
    for (int nt = 0; nt < 4; nt++) {
        const int col = wn * 32 + nt * 8 + 2 * t4;
        const float br0 = b_ih[col],       br1 = b_ih[col + 1];
        const float bz0 = b_ih[128 + col], bz1 = b_ih[128 + col + 1];
        const float bn0 = b_ih[256 + col], bn1 = b_ih[256 + col + 1];
        #pragma unroll
        for (int mt = 0; mt < 2; mt++) {
            const int rbase = rowBase + wm * 32 + mt * 16 + g8;
            #pragma unroll
            for (int half = 0; half < 2; half++) {
                const int row = rbase + half * 8;
                if (row >= NN) continue;
                const int i0 = half * 2;
                float ir0 = c[0][mt][nt][i0]     + br0;
                float ir1 = c[0][mt][nt][i0 + 1] + br1;
                float iz0 = c[1][mt][nt][i0]     + bz0;
                float iz1 = c[1][mt][nt][i0 + 1] + bz1;
                float in0 = c[2][mt][nt][i0]     + bn0;
                float in1 = c[2][mt][nt][i0 + 1] + bn1;
                const __half* ghp = ghb + (size_t)row * 384 + col;
                float2 hr = __half22float2(*(const __half2*)ghp);
                float2 hz = __half22float2(*(const __half2*)(ghp + 128));
                float2 hn = __half22float2(*(const __half2*)(ghp + 256));
                __half2* hp = (__half2*)(hb + (size_t)row * 128 + col);
                float2 h = __half22float2(*hp);
                float r0v = sigf(ir0 + hr.x), z0v = sigf(iz0 + hz.x);
                float n0v = tanhf(in0 + r0v * hn.x);
                float o0 = (1.f - z0v) * n0v + z0v * h.x;
                float r1v = sigf(ir1 + hr.y), z1v = sigf(iz1 + hz.y);
                float n1v = tanhf(in1 + r1v * hn.y);
                float o1 = (1.f - z1v) * n1v + z1v * h.y;
                *hp = __floats2half2_rn(o0, o1);
            }
        }
    }
}

// ---------------- message aggregation (packed CSR edges, from g_t) ----------------
__global__ void aggregate(int g) {
    int w = (blockIdx.x * blockDim.x + threadIdx.x) >> 5;
    if (w >= NN) return;
    int lane = threadIdx.x & 31;
    int s0 = g_indptr[g][w], s1 = g_indptr[g][w + 1];
    const int* pkp = g_pk[g];
    const __half* tb = g_t_h[g];
    float4 acc = make_float4(0.f, 0.f, 0.f, 0.f);
    for (int p = s0; p < s1; p++) {
        int pk = pkp[p];
        int s = pk & 0xffff;
        int k = pk >> 16;
        uint2 v = ((const uint2*)(tb + (size_t)s * (NET * DD) + k * DD))[lane];
        float4 f = h4tof4(v);
        acc.x += f.x; acc.y += f.y; acc.z += f.z; acc.w += f.w;
    }
    ((uint2*)(g_a_h[g] + (size_t)w * DD))[lane] = f4toh4(acc);
}

// ---------------- row L2-normalize + sigmoid ----------------
__global__ void norm_sigmoid(int g) {
    int w = (blockIdx.x * blockDim.x + threadIdx.x) >> 5;
    if (w >= NN) return;
    int lane = threadIdx.x & 31;
    uint2* p = (uint2*)(g_h_h[g] + (size_t)w * 128);
    float4 v = h4tof4(p[lane]);
    float ss = v.x * v.x + v.y * v.y + v.z * v.z + v.w * v.w;
    #pragma unroll
    for (int o = 16; o; o >>= 1) ss += __shfl_xor_sync(0xffffffffu, ss, o);
    float inv = 1.f / fmaxf(sqrtf(ss), 1e-12f);
    v.x = sigf(v.x * inv); v.y = sigf(v.y * inv);
    v.z = sigf(v.z * inv); v.w = sigf(v.w * inv);
    p[lane] = f4toh4(v);
}

// ---------------- GAT attention scalars el/er ----------------
__global__ void elr_kernel(int g, const float* __restrict__ al, const float* __restrict__ ar) {
    int w = (blockIdx.x * blockDim.x + threadIdx.x) >> 5;
    if (w >= NN) return;
    int lane = threadIdx.x & 31;
    const uint2* z2 = (const uint2*)(g_zft_h[g] + (size_t)w * 256);
    const float4* al4 = (const float4*)al;
    const float4* ar4 = (const float4*)ar;
    #pragma unroll
    for (int hd = 0; hd < 2; hd++) {
        float4 zv = h4tof4(z2[hd * 32 + lane]);
        float4 lv = al4[hd * 32 + lane];
        float4 rv = ar4[hd * 32 + lane];
        float pl = zv.x * lv.x + zv.y * lv.y + zv.z * lv.z + zv.w * lv.w;
        float pr = zv.x * rv.x + zv.y * rv.y + zv.z * rv.z + zv.w * rv.w;
        #pragma unroll
        for (int o = 16; o; o >>= 1) {
            pl += __shfl_xor_sync(0xffffffffu, pl, o);
            pr += __shfl_xor_sync(0xffffffffu, pr, o);
        }
        if (lane == 0) { g_el[g][w * 2 + hd] = pl; g_er[g][w * 2 + hd] = pr; }
    }
}

// ---------------- edge weights: exp(leaky(el+er)) scattered into CSR order ----------------
__global__ void edge_w(int g, const int* __restrict__ src, const int* __restrict__ dst) {
    int e = blockIdx.x * blockDim.x + threadIdx.x;
    if (e >= NE) return;
    int s = src[e], d = dst[e];
    int p = g_epos[g][e];
    float2 els = ((const float2*)g_el[g])[s];
    float2 erd = ((const float2*)g_er[g])[d];
    float e0 = els.x + erd.x; e0 = e0 > 0.f ? e0 : 0.2f * e0;
    float e1 = els.y + erd.y; e1 = e1 > 0.f ? e1 : 0.2f * e1;
    ((float2*)g_wgt[g])[p] = make_float2(expf(e0), expf(e1));
}

// ---------------- GAT accumulation: Σ w·zft / Σ w + bias + relu ----------------
__global__ void gat_accum(int g, const float* __restrict__ gbias) {
    int w = (blockIdx.x * blockDim.x + threadIdx.x) >> 5;
    if (w >= NN) return;
    int lane = threadIdx.x & 31;
    int s0 = g_indptr[g][w], s1 = g_indptr[g][w + 1];
    const int* pkp = g_pk[g];
    const float2* wp2 = (const float2*)g_wgt[g];
    const __half* zb = g_zft_h[g];
    float4 a0 = make_float4(0.f,0.f,0.f,0.f), a1 = a0;
    float den0 = 0.f, den1 = 0.f;
    for (int p = s0; p < s1; p++) {
        float2 wv = wp2[p];
        int s = pkp[p] & 0xffff;
        den0 += wv.x; den1 += wv.y;
        const uint2* z2 = (const uint2*)(zb + (size_t)s * 256);
        float4 z0 = h4tof4(z2[lane]), z1 = h4tof4(z2[32 + lane]);
        a0.x += wv.x * z0.x; a0.y += wv.x * z0.y; a0.z += wv.x * z0.z; a0.w += wv.x * z0.w;
        a1.x += wv.y * z1.x; a1.y += wv.y * z1.y; a1.z += wv.y * z1.z; a1.w += wv.y * z1.w;
    }
    float i0 = (den0 > 0.f) ? 1.f / den0 : 0.f;
    float i1 = (den1 > 0.f) ? 1.f / den1 : 0.f;
    const float4* b4 = (const float4*)gbias;
    float4 b0 = b4[lane], b1 = b4[32 + lane];
    float4 o0, o1;
    o0.x = fmaxf(a0.x * i0 + b0.x, 0.f); o0.y = fmaxf(a0.y * i0 + b0.y, 0.f);
    o0.z = fmaxf(a0.z * i0 + b0.z, 0.f); o0.w = fmaxf(a0.w * i0 + b0.w, 0.f);
    o1.x = fmaxf(a1.x * i1 + b1.x, 0.f); o1.y = fmaxf(a1.y * i1 + b1.y, 0.f);
    o1.z = fmaxf(a1.z * i1 + b1.z, 0.f); o1.w = fmaxf(a1.w * i1 + b1.w, 0.f);
    float4* outp = (float4*)(g_rst[g] + (size_t)w * 256);
    outp[lane] = o0;
    outp[32 + lane] = o1;
}

// ---------------- graph bounds ----------------
__global__ void graph_bounds(int g, const int* __restrict__ gid) {
    int b = threadIdx.x;
    if (b > NG) return;
    if (b == NG) { g_gs[g][NG] = NN; return; }
    int lo = 0, hi = NN;
    while (lo < hi) {
        int mid = (lo + hi) >> 1;
        if (gid[mid] < b) lo = mid + 1; else hi = mid;
    }
    g_gs[g][b] = lo;
}

// ---------------- mean pool + classify ----------------
__global__ void pool_classify(int g, const float* __restrict__ Wc, const float* __restrict__ bc) {
    __shared__ float sh[256];
    int b = blockIdx.x;
    int t = threadIdx.x;
    int s = g_gs[g][b], e2 = g_gs[g][b + 1];
    float sum = 0.f;
    const float* rb = g_rst[g];
    for (int r = s; r < e2; r++) sum += rb[(size_t)r * 256 + t];
    sh[t] = sum / fmaxf((float)(e2 - s), 1.f);
    __syncthreads();
    if (t < 64) {
        int hd = t >> 5, c = t & 31;
        float acc = bc[c];
        const float* hp = sh + hd * 128;
        const float* wp = Wc + c * 128;
        #pragma unroll 8
        for (int d2 = 0; d2 < 128; d2++) acc += hp[d2] * wp[d2];
        g_logits[g][(b * 2 + hd) * 32 + c] = acc;
    }
}

// ---------------- final distance + head softmax ----------------
__global__ void final_kernel(float* __restrict__ out) {
    int b = threadIdx.x;
    if (b >= NG) return;
    float dv[2];
    #pragma unroll
    for (int hd = 0; hd < 2; hd++) {
        float ss = 0.f;
        #pragma unroll
        for (int c = 0; c < 32; c++) {
            float df = g_logits[0][(b * 2 + hd) * 32 + c]
                     - g_logits[1][(b * 2 + hd) * 32 + c] + 1e-6f;
            ss += df * df;
        }
        dv[hd] = sqrtf(ss);
    }
    float mx = fmaxf(dv[0], dv[1]);
    float e0 = expf(dv[0] - mx), e1 = expf(dv[1] - mx);
    float inv = 1.f / (e0 + e1);
    out[b * 2] = e0 * inv;
    out[b * 2 + 1] = e1 * inv;
}

// ---------------- host driver ----------------
extern "C" void kernel_launch(void* const* d_in, const int* in_sizes, int n_in,
                              void* d_out, int out_size) {
    const float* in1  = (const float*)d_in[0];
    const float* in2  = (const float*)d_in[1];
    const int* srcA[2] = { (const int*)d_in[2], (const int*)d_in[6] };
    const int* dstA[2] = { (const int*)d_in[3], (const int*)d_in[7] };
    const int* etA [2] = { (const int*)d_in[4], (const int*)d_in[8] };
    const int* gidA[2] = { (const int*)d_in[5], (const int*)d_in[9] };
    const float* featA[2] = { in1, in2 };
    const float* W_et  = (const float*)d_in[10];
    const float* b_et  = (const float*)d_in[11];
    const float* W_ih  = (const float*)d_in[12];
    const float* W_hh  = (const float*)d_in[13];
    const float* b_ih  = (const float*)d_in[14];
    const float* b_hh  = (const float*)d_in[15];
    const float* W_fc  = (const float*)d_in[16];
    const float* al    = (const float*)d_in[17];
    const float* ar    = (const float*)d_in[18];
    const float* gb    = (const float*)d_in[19];
    const float* W_cls = (const float*)d_in[20];
    const float* b_cls = (const float*)d_in[21];

    const int SMEM = 2 * TILE_H2 * 4;
    static int init_done = 0;
    static cudaStream_t st[2];
    static cudaEvent_t evRoot, evDone[2];
    if (!init_done) {
        cudaFuncSetAttribute(gemm_all, cudaFuncAttributeMaxDynamicSharedMemorySize, SMEM);
        cudaFuncSetAttribute(gemm_gru, cudaFuncAttributeMaxDynamicSharedMemorySize, GRU_SMEM);
        cudaStreamCreateWithFlags(&st[0], cudaStreamNonBlocking);
        cudaStreamCreateWithFlags(&st[1], cudaStreamNonBlocking);
        cudaEventCreateWithFlags(&evRoot, cudaEventDisableTiming);
        cudaEventCreateWithFlags(&evDone[0], cudaEventDisableTiming);
        cudaEventCreateWithFlags(&evDone[1], cudaEventDisableTiming);
        init_done = 1;
    }

    // weight conversion on root stream (both branches depend on it)
    {
        __half* p0; cudaGetSymbolAddress((void**)&p0, g_Wet_h);
        __half* p1; cudaGetSymbolAddress((void**)&p1, g_Whh_h);
        __half* p2; cudaGetSymbolAddress((void**)&p2, g_Wih_h);
        __half* p3; cudaGetSymbolAddress((void**)&p3, g_Wfc_h);
        conv_w<<<(NET * DD * DD / 2 + 255) / 256, 256>>>(W_et, p0, NET * DD * DD);
        conv_w<<<(3 * DD * DD / 2 + 255) / 256, 256>>>(W_hh, p1, 3 * DD * DD);
        conv_w<<<(3 * DD * DD / 2 + 255) / 256, 256>>>(W_ih, p2, 3 * DD * DD);
        conv_w<<<(NHEADS * DD * DD / 2 + 255) / 256, 256>>>(W_fc, p3, NHEADS * DD * DD);
    }

    cudaEventRecord(evRoot, 0);

    const int NBLK_E = (NE + 255) / 256;
    const int NBLK_N = (NN + 255) / 256;
    const int NBLK_W = NN / 8;
    const int NBLK_GRU = (NN + 63) / 64;
    const dim3 gFused(391, 7), gZ(391, 2);

    for (int g = 0; g < 2; g++) {
        cudaStream_t s = st[g];
        cudaStreamWaitEvent(s, evRoot, 0);
        const float* feat = featA[g];
        const int* src = srcA[g];
        const int* dst = dstA[g];
        const int* et  = etA[g];
        const int* gid = gidA[g];

        copy_h<<<(NN * 32 + 255) / 256, 256, 0, s>>>(g, feat);
        zero_deg<<<NBLK_N, 256, 0, s>>>(g);
        count_deg<<<NBLK_E, 256, 0, s>>>(g, dst);
        scan1<<<49, 1024, 0, s>>>(g);
        scan2<<<1, 1, 0, s>>>(g);
        scan3<<<49, 1024, 0, s>>>(g);
        build_eids<<<NBLK_E, 256, 0, s>>>(g, src, dst, et);

        for (int it = 0; it < NSTEPS; it++) {
            gemm_all<<<gFused, 256, SMEM, s>>>(0, g, b_et, b_hh);
            aggregate<<<NBLK_W, 256, 0, s>>>(g);
            gemm_gru<<<NBLK_GRU, 256, GRU_SMEM, s>>>(g, b_ih);
        }
        norm_sigmoid<<<NBLK_W, 256, 0, s>>>(g);
        gemm_all<<<gZ, 256, SMEM, s>>>(2, g, nullptr, nullptr);
        elr_kernel<<<NBLK_W, 256, 0, s>>>(g, al, ar);
        edge_w<<<NBLK_E, 256, 0, s>>>(g, src, dst);
        gat_accum<<<NBLK_W, 256, 0, s>>>(g, gb);
        graph_bounds<<<1, NG + 1, 0, s>>>(g, gid);
        pool_classify<<<NG, 256, 0, s>>>(g, W_cls, b_cls);
        cudaEventRecord(evDone[g], s);
    }

    cudaStreamWaitEvent(0, evDone[0], 0);
    cudaStreamWaitEvent(0, evDone[1], 0);
    final_kernel<<<1, NG>>>((float*)d_out);
}